// round 7
// baseline (speedup 1.0000x reference)
#include <cuda_runtime.h>
#include <cstdint>

// Problem constants
#define Bb   2
#define Ss   2048
#define Hh   1024
#define NHh  16
#define HDd  64
#define Mrows (Bb*Ss)   // 4096

// ---------------------------------------------------------------------------
// Device scratch (no allocations allowed). All tf32 payloads stored as u32 bits.
// ---------------------------------------------------------------------------
__device__ uint32_t g_xt[Mrows*Hh];        // X in tf32
__device__ uint32_t g_wt[4*Hh*Hh];         // Wq,Wk,Wv,Wo in tf32
__device__ uint32_t g_qt[Bb*NHh*Ss*HDd];   // Q (pre-scaled by 1/8), tf32, [b,h,s,d]
__device__ uint32_t g_kt[Bb*NHh*Ss*HDd];   // K tf32
__device__ uint32_t g_vt[Bb*NHh*Ss*HDd];   // V tf32
__device__ uint32_t g_ctxt[Bb*Ss*Hh];      // attention output, tf32, [b,s,h]

__device__ __forceinline__ uint32_t f2tf32(float x) {
    uint32_t r;
    asm("cvt.rna.tf32.f32 %0, %1;" : "=r"(r) : "f"(x));
    return r;
}

__device__ __forceinline__ void mma_tf32(float d[4], const uint32_t a[4],
                                         const uint32_t b[2], const float c[4]) {
    asm volatile(
        "mma.sync.aligned.m16n8k8.row.col.f32.tf32.tf32.f32 "
        "{%0,%1,%2,%3}, {%4,%5,%6,%7}, {%8,%9}, {%10,%11,%12,%13};\n"
        : "=f"(d[0]), "=f"(d[1]), "=f"(d[2]), "=f"(d[3])
        : "r"(a[0]), "r"(a[1]), "r"(a[2]), "r"(a[3]),
          "r"(b[0]), "r"(b[1]),
          "f"(c[0]), "f"(c[1]), "f"(c[2]), "f"(c[3]));
}

__device__ __forceinline__ void cp_async16(uint32_t smem_addr, const void* gptr) {
    asm volatile("cp.async.cg.shared.global [%0], [%1], 16;\n"
                 :: "r"(smem_addr), "l"(gptr));
}
__device__ __forceinline__ uint32_t s2u(const void* p) {
    return (uint32_t)__cvta_generic_to_shared(p);
}

// ---------------------------------------------------------------------------
// Prologue: convert X and the 4 weight matrices to tf32 once.
// ---------------------------------------------------------------------------
__global__ __launch_bounds__(256)
void preconv(const float* __restrict__ x,
             const float* __restrict__ wq, const float* __restrict__ wk,
             const float* __restrict__ wv, const float* __restrict__ wo)
{
    const int i = blockIdx.x * blockDim.x + threadIdx.x;
    const int NX4 = (Mrows * Hh) / 4;   // 1,048,576
    const int NW4 = (Hh * Hh) / 4;      // 262,144

    if (i < NX4) {
        float4 v = ((const float4*)x)[i];
        uint4 u;
        u.x = f2tf32(v.x); u.y = f2tf32(v.y);
        u.z = f2tf32(v.z); u.w = f2tf32(v.w);
        ((uint4*)g_xt)[i] = u;
    }
    if (i < NW4) {
        const float* ws[4] = {wq, wk, wv, wo};
#pragma unroll
        for (int z = 0; z < 4; z++) {
            float4 v = ((const float4*)ws[z])[i];
            uint4 u;
            u.x = f2tf32(v.x); u.y = f2tf32(v.y);
            u.z = f2tf32(v.z); u.w = f2tf32(v.w);
            ((uint4*)(g_wt + (size_t)z * Hh * Hh))[i] = u;
        }
    }
}

// ---------------------------------------------------------------------------
// tf32 GEMM with cp.async 2-stage pipeline, v2: 256 threads.
// CTA 128x128, BK=32, 8 warps (4m x 2n), warp tile 32x64.
// Inputs already tf32. dst: 0 -> Yout fp32; 1/2/3 -> g_qt/kt/vt.
// Dynamic SMEM: 2 stages x (A 128x36 + B 128x36) u32 = 73728 bytes.
// ---------------------------------------------------------------------------
#define GEMM_STG   (2*128*36)                 // words per stage (A+B)
#define GEMM_SMEM  (2*GEMM_STG*4)             // bytes

__device__ __forceinline__
void gemm_load_stage(const uint32_t* __restrict__ A, const uint32_t* __restrict__ Bm,
                     uint32_t* dstA, int m0, int n0, int k0, int tid)
{
    uint32_t* dstB = dstA + 128*36;
#pragma unroll
    for (int j = 0; j < 4; j++) {
        const int id  = j * 256 + tid;     // 0..1023
        const int row = id >> 3;
        const int col = (id & 7) * 4;
        cp_async16(s2u(dstA + row*36 + col), A  + (size_t)(m0+row)*Hh + k0 + col);
        cp_async16(s2u(dstB + row*36 + col), Bm + (size_t)(n0+row)*Hh + k0 + col);
    }
}

__device__ __forceinline__
void gemm_tc_body(const uint32_t* __restrict__ A, const uint32_t* __restrict__ Bm,
                  const float* __restrict__ bias, float* __restrict__ Yout,
                  int dst, int bx, int by, uint32_t* smem)
{
    const int tid  = threadIdx.x;
    const int lane = tid & 31;
    const int wid  = tid >> 5;          // 0..7
    const int wm   = (wid & 3) * 32;    // 4 warps along m
    const int wn   = (wid >> 2) * 64;   // 2 warps along n
    const int m0   = by * 128;
    const int n0   = bx * 128;
    const int g    = lane >> 2;
    const int tg   = lane & 3;

    float acc[2][8][4];
#pragma unroll
    for (int mt = 0; mt < 2; mt++)
#pragma unroll
        for (int nt = 0; nt < 8; nt++)
#pragma unroll
            for (int r = 0; r < 4; r++) acc[mt][nt][r] = 0.f;

    gemm_load_stage(A, Bm, smem, m0, n0, 0, tid);
    asm volatile("cp.async.commit_group;\n");

    for (int kt = 0; kt < 32; kt++) {
        if (kt + 1 < 32) {
            gemm_load_stage(A, Bm, smem + ((kt+1)&1)*GEMM_STG, m0, n0, (kt+1)*32, tid);
            asm volatile("cp.async.commit_group;\n");
            asm volatile("cp.async.wait_group 1;\n");
        } else {
            asm volatile("cp.async.wait_group 0;\n");
        }
        __syncthreads();

        const uint32_t* As = smem + (kt & 1) * GEMM_STG;
        const uint32_t* Bs = As + 128*36;

#pragma unroll
        for (int kc = 0; kc < 32; kc += 8) {
            uint32_t af[2][4];
            uint32_t bf[8][2];
#pragma unroll
            for (int mt = 0; mt < 2; mt++) {
                const uint32_t* r0p = As + (wm + mt*16 + g)*36 + kc;
                af[mt][0] = r0p[tg];
                af[mt][2] = r0p[tg + 4];
                const uint32_t* r1p = r0p + 8*36;
                af[mt][1] = r1p[tg];
                af[mt][3] = r1p[tg + 4];
            }
#pragma unroll
            for (int nt = 0; nt < 8; nt++) {
                const uint32_t* cp_ = Bs + (wn + nt*8 + g)*36 + kc;
                bf[nt][0] = cp_[tg];
                bf[nt][1] = cp_[tg + 4];
            }
#pragma unroll
            for (int mt = 0; mt < 2; mt++)
#pragma unroll
                for (int nt = 0; nt < 8; nt++)
                    mma_tf32(acc[mt][nt], af[mt], bf[nt], acc[mt][nt]);
        }
        __syncthreads();
    }

    // epilogue
    const float qscale = (dst == 1) ? 0.125f : 1.0f;
#pragma unroll
    for (int mt = 0; mt < 2; mt++) {
#pragma unroll
        for (int nt = 0; nt < 8; nt++) {
            const int mA = m0 + wm + mt*16 + g;
            const int nA = n0 + wn + nt*8 + tg*2;
            const float b0 = bias[nA], b1 = bias[nA + 1];
#pragma unroll
            for (int half = 0; half < 2; half++) {
                const int m = mA + half * 8;
                float vx = acc[mt][nt][half*2 + 0] + b0;
                float vy = acc[mt][nt][half*2 + 1] + b1;
                if (dst == 0) {
                    float2 v; v.x = vx; v.y = vy;
                    *(float2*)&Yout[(size_t)m * Hh + nA] = v;
                } else {
                    const int bb   = m / Ss;
                    const int s    = m - bb * Ss;
                    const int head = nA >> 6;
                    const int d    = nA & 63;
                    uint32_t* dp = (dst == 1) ? g_qt : (dst == 2) ? g_kt : g_vt;
                    uint2 u;
                    u.x = f2tf32(vx * qscale);
                    u.y = f2tf32(vy * qscale);
                    *(uint2*)&dp[(((size_t)(bb * NHh + head)) * Ss + s) * HDd + d] = u;
                }
            }
        }
    }
}

__global__ __launch_bounds__(256)
void gemm_qkv(const float* __restrict__ bq, const float* __restrict__ bk,
              const float* __restrict__ bv)
{
    extern __shared__ uint32_t smem_g[];
    const int z = blockIdx.z;
    const float* bias = (z == 0) ? bq : (z == 1) ? bk : bv;
    gemm_tc_body(g_xt, g_wt + (size_t)z * Hh * Hh, bias, nullptr,
                 z + 1, blockIdx.x, blockIdx.y, smem_g);
}

__global__ __launch_bounds__(256)
void gemm_out(const float* __restrict__ bo, float* __restrict__ out)
{
    extern __shared__ uint32_t smem_g[];
    gemm_tc_body(g_ctxt, g_wt + (size_t)3 * Hh * Hh, bo, out,
                 0, blockIdx.x, blockIdx.y, smem_g);
}

// ---------------------------------------------------------------------------
// Tensor-core causal flash attention (tf32 mma), unchanged from round 6.
// grid: (S/64, B*NH), block 128 (4 warps). Heavy q-tiles first.
// Dynamic SMEM: Ks 64x68 + Vs 64x72 + Ps 64x68 = 53248 bytes.
// ---------------------------------------------------------------------------
#define ATTN_SMEM ((64*68 + 64*72 + 64*68)*4)

__global__ __launch_bounds__(128)
void attn_tc()
{
    extern __shared__ uint32_t asmem[];
    uint32_t (*Ks)[68] = (uint32_t(*)[68])asmem;                    // Q staging / K tile
    uint32_t (*Vs)[72] = (uint32_t(*)[72])(asmem + 64*68);          // V tile
    uint32_t (*Ps)[68] = (uint32_t(*)[68])(asmem + 64*68 + 64*72);  // P tile

    const int tid  = threadIdx.x;
    const int lane = tid & 31;
    const int wid  = tid >> 5;      // 0..3
    const int g    = lane >> 2;     // 0..7
    const int tg   = lane & 3;      // 0..3
    const int qb   = gridDim.x - 1 - blockIdx.x;   // heavy tiles first
    const int bh   = blockIdx.y;
    const int q0   = qb * 64;
    const int R0   = wid * 16;      // warp's q-row base within tile

    const uint32_t* Qg = g_qt + (size_t)bh * Ss * HDd;
    const uint32_t* Kg = g_kt + (size_t)bh * Ss * HDd;
    const uint32_t* Vg = g_vt + (size_t)bh * Ss * HDd;

    // ---- stage Q into Ks (already tf32 + pre-scaled), pull fragments ----
    for (int u = tid; u < 64 * 16; u += 128) {
        const int r = u >> 4;
        const int c = (u & 15) << 2;
        *(uint4*)&Ks[r][c] = *(const uint4*)&Qg[(size_t)(q0 + r) * 64 + c];
    }
    __syncthreads();

    uint32_t qf[8][4];
#pragma unroll
    for (int kc = 0; kc < 8; kc++) {
        qf[kc][0] = Ks[R0 + g][kc * 8 + tg];
        qf[kc][1] = Ks[R0 + g + 8][kc * 8 + tg];
        qf[kc][2] = Ks[R0 + g][kc * 8 + tg + 4];
        qf[kc][3] = Ks[R0 + g + 8][kc * 8 + tg + 4];
    }

    float oacc[8][4];
#pragma unroll
    for (int nt = 0; nt < 8; nt++)
#pragma unroll
        for (int r = 0; r < 4; r++) oacc[nt][r] = 0.f;
    float m0 = -1e30f, m1 = -1e30f, l0 = 0.f, l1 = 0.f;

    for (int kb = 0; kb <= qb; kb++) {
        const int k0 = kb * 64;
        __syncthreads();   // prev tile's Ks/Vs/Ps reads complete (and Q frags, kb=0)

        // ---- load K tile -> Ks, V tile -> Vs (pure uint4 copies) ----
        for (int u = tid; u < 64 * 16; u += 128) {
            const int r = u >> 4;
            const int c = (u & 15) << 2;
            *(uint4*)&Ks[r][c] = *(const uint4*)&Kg[(size_t)(k0 + r) * 64 + c];
            *(uint4*)&Vs[r][c] = *(const uint4*)&Vg[(size_t)(k0 + r) * 64 + c];
        }
        __syncthreads();

        // ---- S = Q K^T (Q pre-scaled) ----
        float sacc[8][4];
#pragma unroll
        for (int nt = 0; nt < 8; nt++)
#pragma unroll
            for (int r = 0; r < 4; r++) sacc[nt][r] = 0.f;

#pragma unroll
        for (int kc = 0; kc < 8; kc++) {
#pragma unroll
            for (int nt = 0; nt < 8; nt++) {
                uint32_t kf[2];
                kf[0] = Ks[nt * 8 + g][kc * 8 + tg];
                kf[1] = Ks[nt * 8 + g][kc * 8 + tg + 4];
                mma_tf32(sacc[nt], qf[kc], kf, sacc[nt]);
            }
        }

        // ---- causal mask on diagonal tile ----
        if (kb == qb) {
            const int r0 = R0 + g;
            const int r1 = r0 + 8;
#pragma unroll
            for (int nt = 0; nt < 8; nt++) {
                const int c0 = nt * 8 + tg * 2;
                if (c0 > r0)     sacc[nt][0] = -1e30f;
                if (c0 + 1 > r0) sacc[nt][1] = -1e30f;
                if (c0 > r1)     sacc[nt][2] = -1e30f;
                if (c0 + 1 > r1) sacc[nt][3] = -1e30f;
            }
        }

        // ---- online softmax: row max ----
        float bm0 = -1e30f, bm1 = -1e30f;
#pragma unroll
        for (int nt = 0; nt < 8; nt++) {
            bm0 = fmaxf(bm0, fmaxf(sacc[nt][0], sacc[nt][1]));
            bm1 = fmaxf(bm1, fmaxf(sacc[nt][2], sacc[nt][3]));
        }
        bm0 = fmaxf(bm0, __shfl_xor_sync(0xffffffffu, bm0, 1));
        bm0 = fmaxf(bm0, __shfl_xor_sync(0xffffffffu, bm0, 2));
        bm1 = fmaxf(bm1, __shfl_xor_sync(0xffffffffu, bm1, 1));
        bm1 = fmaxf(bm1, __shfl_xor_sync(0xffffffffu, bm1, 2));

        const float nm0 = fmaxf(m0, bm0);
        const float nm1 = fmaxf(m1, bm1);
        const float c0f = __expf(m0 - nm0);
        const float c1f = __expf(m1 - nm1);
        m0 = nm0; m1 = nm1;
#pragma unroll
        for (int nt = 0; nt < 8; nt++) {
            oacc[nt][0] *= c0f; oacc[nt][1] *= c0f;
            oacc[nt][2] *= c1f; oacc[nt][3] *= c1f;
        }
        l0 *= c0f; l1 *= c1f;

        // ---- P = exp(S - m) -> Ps (own warp stripe; no cross-warp use) ----
        float rs0 = 0.f, rs1 = 0.f;
#pragma unroll
        for (int nt = 0; nt < 8; nt++) {
            const int cc = nt * 8 + tg * 2;
            float p0 = __expf(sacc[nt][0] - nm0);
            float p1 = __expf(sacc[nt][1] - nm0);
            float p2 = __expf(sacc[nt][2] - nm1);
            float p3 = __expf(sacc[nt][3] - nm1);
            rs0 += p0 + p1;
            rs1 += p2 + p3;
            Ps[R0 + g][cc]         = f2tf32(p0);
            Ps[R0 + g][cc + 1]     = f2tf32(p1);
            Ps[R0 + g + 8][cc]     = f2tf32(p2);
            Ps[R0 + g + 8][cc + 1] = f2tf32(p3);
        }
        rs0 += __shfl_xor_sync(0xffffffffu, rs0, 1);
        rs0 += __shfl_xor_sync(0xffffffffu, rs0, 2);
        rs1 += __shfl_xor_sync(0xffffffffu, rs1, 1);
        rs1 += __shfl_xor_sync(0xffffffffu, rs1, 2);
        l0 += rs0; l1 += rs1;

        __syncwarp();      // P stripe visible within warp

        // ---- O += P @ V ----
#pragma unroll
        for (int kc = 0; kc < 8; kc++) {
            uint32_t af[4];
            af[0] = Ps[R0 + g][kc * 8 + tg];
            af[1] = Ps[R0 + g + 8][kc * 8 + tg];
            af[2] = Ps[R0 + g][kc * 8 + tg + 4];
            af[3] = Ps[R0 + g + 8][kc * 8 + tg + 4];
#pragma unroll
            for (int nt = 0; nt < 8; nt++) {
                uint32_t bf[2];
                bf[0] = Vs[kc * 8 + tg][nt * 8 + g];
                bf[1] = Vs[kc * 8 + tg + 4][nt * 8 + g];
                mma_tf32(oacc[nt], af, bf, oacc[nt]);
            }
        }
    }

    // ---- normalize + writeback ctx (tf32) ----
    const float inv0 = 1.f / l0;
    const float inv1 = 1.f / l1;
    const int b    = bh / NHh;
    const int head = bh - b * NHh;
    const int s0   = q0 + R0 + g;
    const int s1   = s0 + 8;
#pragma unroll
    for (int nt = 0; nt < 8; nt++) {
        const int col = head * 64 + nt * 8 + tg * 2;
        uint2 v0, v1;
        v0.x = f2tf32(oacc[nt][0] * inv0); v0.y = f2tf32(oacc[nt][1] * inv0);
        v1.x = f2tf32(oacc[nt][2] * inv1); v1.y = f2tf32(oacc[nt][3] * inv1);
        *(uint2*)&g_ctxt[((size_t)(b * Ss) + s0) * Hh + col] = v0;
        *(uint2*)&g_ctxt[((size_t)(b * Ss) + s1) * Hh + col] = v1;
    }
}

// ---------------------------------------------------------------------------
// kernel_launch
// inputs: 0 hidden_states, 1 Wq, 2 bq, 3 Wk, 4 bk, 5 Wv, 6 bv, 7 Wo, 8 bo
// ---------------------------------------------------------------------------
extern "C" void kernel_launch(void* const* d_in, const int* in_sizes, int n_in,
                              void* d_out, int out_size)
{
    const float* x  = (const float*)d_in[0];
    const float* Wq = (const float*)d_in[1];
    const float* bq = (const float*)d_in[2];
    const float* Wk = (const float*)d_in[3];
    const float* bk = (const float*)d_in[4];
    const float* Wv = (const float*)d_in[5];
    const float* bv = (const float*)d_in[6];
    const float* Wo = (const float*)d_in[7];
    const float* bo = (const float*)d_in[8];
    float* out = (float*)d_out;

    cudaFuncSetAttribute(gemm_qkv, cudaFuncAttributeMaxDynamicSharedMemorySize, GEMM_SMEM);
    cudaFuncSetAttribute(gemm_out, cudaFuncAttributeMaxDynamicSharedMemorySize, GEMM_SMEM);
    cudaFuncSetAttribute(attn_tc,  cudaFuncAttributeMaxDynamicSharedMemorySize, ATTN_SMEM);

    preconv<<<4096, 256>>>(x, Wq, Wk, Wv, Wo);

    dim3 qkvgrid(Hh / 128, Mrows / 128, 3);   // (8, 32, 3)
    gemm_qkv<<<qkvgrid, 256, GEMM_SMEM>>>(bq, bk, bv);

    dim3 agrid(Ss / 64, Bb * NHh);            // (32, 32)
    attn_tc<<<agrid, 128, ATTN_SMEM>>>();

    dim3 ogrid(Hh / 128, Mrows / 128);        // (8, 32)
    gemm_out<<<ogrid, 256, GEMM_SMEM>>>(bo, out);
}